// round 1
// baseline (speedup 1.0000x reference)
#include <cuda_runtime.h>

// GatedIndRnnCell: B=8192, IN=H=2048
//   pre_gate = concat(input,state) @ gate_w^T + bias      [B,H], K=4096
//   gate     = clip(pre_gate, 0, 1)
//   values   = tanh(input @ w_i^T)                        [B,H], K=2048
//   pre_h    = state*(1-gate) + values*gate
//   new_h    = relu(pre_h)
// Outputs flattened in tuple order:
//   new_h [B,H], concat [B,IN+H], pre_gate [B,H], gate [B,H], values [B,H], pre_h [B,H]

namespace {
constexpr int Bb  = 8192;
constexpr int INN = 2048;
constexpr int HH  = 2048;
constexpr int KG  = INN + HH;  // 4096

constexpr int BM = 128, BN = 128, BK = 16, TM = 8, TN = 8;
constexpr int NTHREADS = (BM / TM) * (BN / TN);  // 256
}

// ---------------------------------------------------------------------------
// Kernel 1: values = tanh(input @ w_i^T)     (M=B, N=H, K=IN; both K-major)
// ---------------------------------------------------------------------------
__global__ __launch_bounds__(NTHREADS) void values_gemm(
    const float* __restrict__ A,      // [B, IN]
    const float* __restrict__ W,      // [H, IN]
    float* __restrict__ values)       // [B, H]
{
    __shared__ float As[BK][BM + 4];
    __shared__ float Bs[BK][BN + 4];

    const int bm = blockIdx.y * BM;
    const int bn = blockIdx.x * BN;
    const int t  = threadIdx.x;
    const int tx = t & 15;        // 0..15  -> N direction
    const int ty = t >> 4;        // 0..15  -> M direction
    const int lr = t >> 2;        // 0..63  loader row
    const int lc = (t & 3) << 2;  // 0,4,8,12 loader col (x4)

    float acc[TM][TN] = {};

    for (int kk = 0; kk < INN; kk += BK) {
        float4 a0 = *(const float4*)(&A[(size_t)(bm + lr) * INN + kk + lc]);
        float4 a1 = *(const float4*)(&A[(size_t)(bm + lr + 64) * INN + kk + lc]);
        float4 w0 = *(const float4*)(&W[(size_t)(bn + lr) * INN + kk + lc]);
        float4 w1 = *(const float4*)(&W[(size_t)(bn + lr + 64) * INN + kk + lc]);

        As[lc + 0][lr] = a0.x; As[lc + 1][lr] = a0.y;
        As[lc + 2][lr] = a0.z; As[lc + 3][lr] = a0.w;
        As[lc + 0][lr + 64] = a1.x; As[lc + 1][lr + 64] = a1.y;
        As[lc + 2][lr + 64] = a1.z; As[lc + 3][lr + 64] = a1.w;
        Bs[lc + 0][lr] = w0.x; Bs[lc + 1][lr] = w0.y;
        Bs[lc + 2][lr] = w0.z; Bs[lc + 3][lr] = w0.w;
        Bs[lc + 0][lr + 64] = w1.x; Bs[lc + 1][lr + 64] = w1.y;
        Bs[lc + 2][lr + 64] = w1.z; Bs[lc + 3][lr + 64] = w1.w;
        __syncthreads();

        #pragma unroll
        for (int k = 0; k < BK; k++) {
            float ra[TM], rb[TN];
            #pragma unroll
            for (int i = 0; i < TM; i++) ra[i] = As[k][ty * TM + i];
            #pragma unroll
            for (int j = 0; j < TN; j++) rb[j] = Bs[k][tx * TN + j];
            #pragma unroll
            for (int i = 0; i < TM; i++)
                #pragma unroll
                for (int j = 0; j < TN; j++)
                    acc[i][j] = fmaf(ra[i], rb[j], acc[i][j]);
        }
        __syncthreads();
    }

    #pragma unroll
    for (int i = 0; i < TM; i++) {
        const size_t row = (size_t)(bm + ty * TM + i) * HH;
        #pragma unroll
        for (int jj = 0; jj < TN; jj += 4) {
            const int n = bn + tx * TN + jj;
            float4 v;
            v.x = tanhf(acc[i][jj + 0]);
            v.y = tanhf(acc[i][jj + 1]);
            v.z = tanhf(acc[i][jj + 2]);
            v.w = tanhf(acc[i][jj + 3]);
            *(float4*)(&values[row + n]) = v;
        }
    }
}

// ---------------------------------------------------------------------------
// Kernel 2: gate GEMM over K=4096 (A = input for k<IN, state for k>=IN),
// fused epilogue computing pre_gate, gate, pre_h, new_h.
// ---------------------------------------------------------------------------
__global__ __launch_bounds__(NTHREADS) void gate_gemm(
    const float* __restrict__ input,    // [B, IN]
    const float* __restrict__ state,    // [B, H]
    const float* __restrict__ Wg,       // [H, IN+H]
    const float* __restrict__ bias,     // [H]
    const float* __restrict__ values,   // [B, H] (from kernel 1)
    float* __restrict__ pre_gate,       // [B, H]
    float* __restrict__ gate,           // [B, H]
    float* __restrict__ pre_h,          // [B, H]
    float* __restrict__ new_h)          // [B, H]
{
    __shared__ float As[BK][BM + 4];
    __shared__ float Bs[BK][BN + 4];

    const int bm = blockIdx.y * BM;
    const int bn = blockIdx.x * BN;
    const int t  = threadIdx.x;
    const int tx = t & 15;
    const int ty = t >> 4;
    const int lr = t >> 2;
    const int lc = (t & 3) << 2;

    float acc[TM][TN] = {};

    for (int kk = 0; kk < KG; kk += BK) {
        const float* Abase = (kk < INN) ? input : state;
        const int acol = (kk < INN) ? kk : (kk - INN);

        float4 a0 = *(const float4*)(&Abase[(size_t)(bm + lr) * INN + acol + lc]);
        float4 a1 = *(const float4*)(&Abase[(size_t)(bm + lr + 64) * INN + acol + lc]);
        float4 w0 = *(const float4*)(&Wg[(size_t)(bn + lr) * KG + kk + lc]);
        float4 w1 = *(const float4*)(&Wg[(size_t)(bn + lr + 64) * KG + kk + lc]);

        As[lc + 0][lr] = a0.x; As[lc + 1][lr] = a0.y;
        As[lc + 2][lr] = a0.z; As[lc + 3][lr] = a0.w;
        As[lc + 0][lr + 64] = a1.x; As[lc + 1][lr + 64] = a1.y;
        As[lc + 2][lr + 64] = a1.z; As[lc + 3][lr + 64] = a1.w;
        Bs[lc + 0][lr] = w0.x; Bs[lc + 1][lr] = w0.y;
        Bs[lc + 2][lr] = w0.z; Bs[lc + 3][lr] = w0.w;
        Bs[lc + 0][lr + 64] = w1.x; Bs[lc + 1][lr + 64] = w1.y;
        Bs[lc + 2][lr + 64] = w1.z; Bs[lc + 3][lr + 64] = w1.w;
        __syncthreads();

        #pragma unroll
        for (int k = 0; k < BK; k++) {
            float ra[TM], rb[TN];
            #pragma unroll
            for (int i = 0; i < TM; i++) ra[i] = As[k][ty * TM + i];
            #pragma unroll
            for (int j = 0; j < TN; j++) rb[j] = Bs[k][tx * TN + j];
            #pragma unroll
            for (int i = 0; i < TM; i++)
                #pragma unroll
                for (int j = 0; j < TN; j++)
                    acc[i][j] = fmaf(ra[i], rb[j], acc[i][j]);
        }
        __syncthreads();
    }

    #pragma unroll
    for (int i = 0; i < TM; i++) {
        const size_t row = (size_t)(bm + ty * TM + i) * HH;
        #pragma unroll
        for (int jj = 0; jj < TN; jj += 4) {
            const int n = bn + tx * TN + jj;

            float bi[4], sv[4], vv[4];
            *(float4*)bi = *(const float4*)(&bias[n]);
            *(float4*)sv = *(const float4*)(&state[row + n]);
            *(float4*)vv = *(const float4*)(&values[row + n]);

            float pg[4], g[4], ph[4], nh[4];
            #pragma unroll
            for (int c = 0; c < 4; c++) {
                pg[c] = acc[i][jj + c] + bi[c];
                g[c]  = fminf(fmaxf(pg[c], 0.0f), 1.0f);
                // state*(1-g) + values*g
                ph[c] = sv[c] * (1.0f - g[c]) + vv[c] * g[c];
                nh[c] = fmaxf(ph[c], 0.0f);
            }
            *(float4*)(&pre_gate[row + n]) = *(float4*)pg;
            *(float4*)(&gate[row + n])     = *(float4*)g;
            *(float4*)(&pre_h[row + n])    = *(float4*)ph;
            *(float4*)(&new_h[row + n])    = *(float4*)nh;
        }
    }
}

// ---------------------------------------------------------------------------
// Kernel 3: concat_input[b] = [input[b], state[b]]   (pure copy, float4)
// ---------------------------------------------------------------------------
__global__ __launch_bounds__(256) void concat_kernel(
    const float4* __restrict__ in4,   // [B, IN/4]
    const float4* __restrict__ st4,   // [B, H/4]
    float4* __restrict__ out4)        // [B, (IN+H)/4]
{
    const int idx = blockIdx.x * blockDim.x + threadIdx.x;  // over B * 1024
    const int row = idx >> 10;          // (IN+H)/4 = 1024 float4 per row
    const int c   = idx & 1023;
    float4 v;
    if (c < (INN / 4))
        v = in4[(size_t)row * (INN / 4) + c];
    else
        v = st4[(size_t)row * (HH / 4) + (c - INN / 4)];
    out4[idx] = v;
}

extern "C" void kernel_launch(void* const* d_in, const int* in_sizes, int n_in,
                              void* d_out, int out_size) {
    const float* input  = (const float*)d_in[0];  // [B, IN]
    const float* state  = (const float*)d_in[1];  // [B, H]
    const float* gate_w = (const float*)d_in[2];  // [H, IN+H]
    const float* gate_b = (const float*)d_in[3];  // [H]
    const float* w_i    = (const float*)d_in[4];  // [H, IN]

    float* out = (float*)d_out;
    float* new_h    = out;
    float* concat   = new_h + (size_t)Bb * HH;
    float* pre_gate = concat + (size_t)Bb * (INN + HH);
    float* gate     = pre_gate + (size_t)Bb * HH;
    float* values   = gate + (size_t)Bb * HH;
    float* pre_h    = values + (size_t)Bb * HH;

    dim3 grid(HH / BN, Bb / BM);   // (16, 64)
    dim3 block(NTHREADS);

    values_gemm<<<grid, block>>>(input, w_i, values);
    gate_gemm<<<grid, block>>>(input, state, gate_w, gate_b, values,
                               pre_gate, gate, pre_h, new_h);

    const int n4 = Bb * ((INN + HH) / 4);  // 8,388,608 float4s
    concat_kernel<<<n4 / 256, 256>>>((const float4*)input, (const float4*)state,
                                     (float4*)concat);
}

// round 3
// speedup vs baseline: 3.2670x; 3.2670x over previous
#include <cuda_runtime.h>
#include <cuda_bf16.h>
#include <cstdint>

#define DI __device__ __forceinline__

namespace {
constexpr int Bb = 8192, INN = 2048, HH = 2048, KG = 4096;
constexpr int BM = 128, BN = 128, BK = 64;       // bf16 elems per K-chunk
constexpr int NTH = 256;                          // 8 warps: 2 (M) x 4 (N)
constexpr int STG_BYTES = 64 * 1024;              // Ah/Al/Wh/Wl 16KB each
constexpr int OFF_AL = 16384, OFF_WH = 32768, OFF_WL = 49152;
constexpr int SMEM_TOTAL = 2 * STG_BYTES;         // 128KB double-buffered
}

// bf16 hi/lo scratch
__device__ __align__(1024) __nv_bfloat16 g_CAhi[(size_t)Bb * KG];
__device__ __align__(1024) __nv_bfloat16 g_CAlo[(size_t)Bb * KG];
__device__ __align__(1024) __nv_bfloat16 g_Wghi[(size_t)HH * KG];
__device__ __align__(1024) __nv_bfloat16 g_Wglo[(size_t)HH * KG];
__device__ __align__(1024) __nv_bfloat16 g_Wihi[(size_t)HH * INN];
__device__ __align__(1024) __nv_bfloat16 g_Wilo[(size_t)HH * INN];

// ---------------- PTX helpers (all portable to compute_103) ----------------
DI uint32_t smem_u32(const void* p) {
    uint32_t a;
    asm("{ .reg .u64 t; cvta.to.shared.u64 t, %1; cvt.u32.u64 %0, t; }" : "=r"(a) : "l"(p));
    return a;
}
DI void cp16(uint32_t s, const void* g) {
    asm volatile("cp.async.cg.shared.global [%0], [%1], 16;" :: "r"(s), "l"(g) : "memory");
}
DI void cp_commit() { asm volatile("cp.async.commit_group;" ::: "memory"); }
template <int N>
DI void cp_wait() { asm volatile("cp.async.wait_group %0;" :: "n"(N) : "memory"); }

DI void ldsm_x4(uint32_t* r, uint32_t addr) {
    asm volatile("ldmatrix.sync.aligned.m8n8.x4.shared.b16 {%0,%1,%2,%3}, [%4];"
                 : "=r"(r[0]), "=r"(r[1]), "=r"(r[2]), "=r"(r[3]) : "r"(addr));
}
DI void mma_bf16(float* d, const uint32_t* a, const uint32_t* b) {
    asm volatile(
        "mma.sync.aligned.m16n8k16.row.col.f32.bf16.bf16.f32 "
        "{%0,%1,%2,%3}, {%4,%5,%6,%7}, {%8,%9}, {%0,%1,%2,%3};"
        : "+f"(d[0]), "+f"(d[1]), "+f"(d[2]), "+f"(d[3])
        : "r"(a[0]), "r"(a[1]), "r"(a[2]), "r"(a[3]), "r"(b[0]), "r"(b[1]));
}

// swizzled byte offset for (row, 16B-chunk c16) in a 128B-row tile
DI uint32_t swz(int row, int c16) {
    return (uint32_t)(row * 128 + ((c16 ^ (row & 7)) << 4));
}

// ---------------- conversion kernels ----------------
DI void hilo4(float4 v, __nv_bfloat162* h, __nv_bfloat162* l) {
    __nv_bfloat162 h0 = __floats2bfloat162_rn(v.x, v.y);
    __nv_bfloat162 h1 = __floats2bfloat162_rn(v.z, v.w);
    float r0 = v.x - __low2float(h0), r1 = v.y - __high2float(h0);
    float r2 = v.z - __low2float(h1), r3 = v.w - __high2float(h1);
    h[0] = h0; h[1] = h1;
    l[0] = __floats2bfloat162_rn(r0, r1);
    l[1] = __floats2bfloat162_rn(r2, r3);
}

__global__ __launch_bounds__(256) void convertA(
    const float4* __restrict__ in4, const float4* __restrict__ st4,
    float4* __restrict__ concat4)
{
    int idx = blockIdx.x * blockDim.x + threadIdx.x;  // Bb*512
    int row = idx >> 9, c4 = idx & 511;

    float4 vi = in4[(size_t)row * 512 + c4];
    concat4[(size_t)row * 1024 + c4] = vi;
    size_t off = (size_t)row * KG + (size_t)c4 * 4;
    hilo4(vi, (__nv_bfloat162*)(g_CAhi + off), (__nv_bfloat162*)(g_CAlo + off));

    float4 vs = st4[(size_t)row * 512 + c4];
    concat4[(size_t)row * 1024 + 512 + c4] = vs;
    off += INN;
    hilo4(vs, (__nv_bfloat162*)(g_CAhi + off), (__nv_bfloat162*)(g_CAlo + off));
}

__global__ __launch_bounds__(256) void convertW(
    const float4* __restrict__ src, __nv_bfloat16* __restrict__ hi,
    __nv_bfloat16* __restrict__ lo, int n4)
{
    int idx = blockIdx.x * blockDim.x + threadIdx.x;
    if (idx >= n4) return;
    float4 v = src[idx];
    size_t off = (size_t)idx * 4;
    hilo4(v, (__nv_bfloat162*)(hi + off), (__nv_bfloat162*)(lo + off));
}

// ---------------- GEMM via mma.sync ----------------
DI void load_stage(uint32_t st,
                   const __nv_bfloat16* __restrict__ Ahi, const __nv_bfloat16* __restrict__ Alo,
                   const __nv_bfloat16* __restrict__ Whi, const __nv_bfloat16* __restrict__ Wlo,
                   int lda, int ldw, int bm, int bn, int kc, int t)
{
    // per array: 4 cp16/thread: rows (t>>2)+64j, c16 (t&3)+4i
    const int r0 = t >> 2, cc = t & 3;
    #pragma unroll
    for (int j = 0; j < 2; j++) {
        const int r = r0 + 64 * j;
        const char* pAh = (const char*)(Ahi + (size_t)(bm + r) * lda + kc);
        const char* pAl = (const char*)(Alo + (size_t)(bm + r) * lda + kc);
        const char* pWh = (const char*)(Whi + (size_t)(bn + r) * ldw + kc);
        const char* pWl = (const char*)(Wlo + (size_t)(bn + r) * ldw + kc);
        #pragma unroll
        for (int i = 0; i < 2; i++) {
            const int c16 = cc + 4 * i;
            const uint32_t so = swz(r, c16);
            cp16(st + so,          pAh + c16 * 16);
            cp16(st + OFF_AL + so, pAl + c16 * 16);
            cp16(st + OFF_WH + so, pWh + c16 * 16);
            cp16(st + OFF_WL + so, pWl + c16 * 16);
        }
    }
}

template <bool GATE>
__global__ __launch_bounds__(NTH, 1)
void gemm_mma(const __nv_bfloat16* __restrict__ Ahi, const __nv_bfloat16* __restrict__ Alo,
              const __nv_bfloat16* __restrict__ Whi, const __nv_bfloat16* __restrict__ Wlo,
              int kdim,
              const float* __restrict__ state, const float* __restrict__ bias,
              const float* __restrict__ values_in,
              float* __restrict__ out0,
              float* __restrict__ gate_o, float* __restrict__ pre_h_o,
              float* __restrict__ new_h_o)
{
    extern __shared__ char smem[];
    const uint32_t sb = smem_u32(smem);
    const int t = threadIdx.x, wid = t >> 5, lane = t & 31;
    const int warp_m = wid >> 2, warp_n = wid & 3;      // 2 x 4
    const int bm = blockIdx.y * BM, bn = blockIdx.x * BN;

    float acc[4][4][4] = {};   // [mtile][ntile][frag]

    const int nch = kdim / BK;
    load_stage(sb, Ahi, Alo, Whi, Wlo, KG, kdim, bm, bn, 0, t);
    cp_commit();

    // precomputed ldmatrix lane addressing
    const int a_row = warp_m * 64 + (lane & 15);        // + mt*16
    const int a_chi = lane >> 4;                        // c16 += 2s
    const int lm = lane >> 3;                           // matrix idx for B x4
    const int b_row = warp_n * 32 + (lane & 7) + ((lm >> 1) << 3);  // + np*16
    const int b_chi = lm & 1;

    for (int k = 0; k < nch; k++) {
        if (k + 1 < nch) {
            load_stage(sb + ((k + 1) & 1) * STG_BYTES, Ahi, Alo, Whi, Wlo,
                       KG, kdim, bm, bn, (k + 1) * BK, t);
            cp_commit();
            cp_wait<1>();
        } else {
            cp_wait<0>();
        }
        __syncthreads();

        const uint32_t st = sb + (k & 1) * STG_BYTES;
        #pragma unroll
        for (int s = 0; s < 4; s++) {
            uint32_t ah[4][4], al[4][4];
            #pragma unroll
            for (int mt = 0; mt < 4; mt++) {
                const uint32_t off = swz(a_row + mt * 16, 2 * s + a_chi);
                ldsm_x4(ah[mt], st + off);
                ldsm_x4(al[mt], st + OFF_AL + off);
            }
            uint32_t bh[2][4], bl[2][4];
            #pragma unroll
            for (int np = 0; np < 2; np++) {
                const uint32_t off = swz(b_row + np * 16, 2 * s + b_chi);
                ldsm_x4(bh[np], st + OFF_WH + off);
                ldsm_x4(bl[np], st + OFF_WL + off);
            }
            #pragma unroll
            for (int mt = 0; mt < 4; mt++)
                #pragma unroll
                for (int nt = 0; nt < 4; nt++) {
                    const uint32_t* ph = bh[nt >> 1] + (nt & 1) * 2;
                    const uint32_t* pl = bl[nt >> 1] + (nt & 1) * 2;
                    mma_bf16(acc[mt][nt], ah[mt], ph);
                    mma_bf16(acc[mt][nt], ah[mt], pl);
                    mma_bf16(acc[mt][nt], al[mt], ph);
                }
        }
        __syncthreads();
    }

    // epilogue: fragment layout -> float2 stores
    const int er = bm + warp_m * 64 + (lane >> 2);      // +mt*16, +8 for c2/c3
    const int ec = bn + warp_n * 32 + (lane & 3) * 2;   // +nt*8

    #pragma unroll
    for (int mt = 0; mt < 4; mt++) {
        #pragma unroll
        for (int half = 0; half < 2; half++) {
            const size_t row = (size_t)(er + mt * 16 + half * 8) * HH;
            #pragma unroll
            for (int nt = 0; nt < 4; nt++) {
                const int n = ec + nt * 8;
                const float* a2 = &acc[mt][nt][half * 2];
                if (!GATE) {
                    float2 v = { tanhf(a2[0]), tanhf(a2[1]) };
                    *(float2*)(&out0[row + n]) = v;
                } else {
                    float2 bi = *(const float2*)(&bias[n]);
                    float2 sv = *(const float2*)(&state[row + n]);
                    float2 vv = *(const float2*)(&values_in[row + n]);
                    float2 pg = { a2[0] + bi.x, a2[1] + bi.y };
                    float2 g  = { fminf(fmaxf(pg.x, 0.f), 1.f), fminf(fmaxf(pg.y, 0.f), 1.f) };
                    float2 ph = { sv.x * (1.f - g.x) + vv.x * g.x,
                                  sv.y * (1.f - g.y) + vv.y * g.y };
                    float2 nh = { fmaxf(ph.x, 0.f), fmaxf(ph.y, 0.f) };
                    *(float2*)(&out0[row + n])    = pg;
                    *(float2*)(&gate_o[row + n])  = g;
                    *(float2*)(&pre_h_o[row + n]) = ph;
                    *(float2*)(&new_h_o[row + n]) = nh;
                }
            }
        }
    }
}

// ---------------- launch ----------------
extern "C" void kernel_launch(void* const* d_in, const int* in_sizes, int n_in,
                              void* d_out, int out_size) {
    const float* input  = (const float*)d_in[0];
    const float* state  = (const float*)d_in[1];
    const float* gate_w = (const float*)d_in[2];
    const float* gate_b = (const float*)d_in[3];
    const float* w_i    = (const float*)d_in[4];

    float* out = (float*)d_out;
    float* new_h    = out;
    float* concat   = new_h + (size_t)Bb * HH;
    float* pre_gate = concat + (size_t)Bb * KG;
    float* gate     = pre_gate + (size_t)Bb * HH;
    float* values   = gate + (size_t)Bb * HH;
    float* pre_h    = values + (size_t)Bb * HH;

    void *cahi, *calo, *wghi, *wglo, *wihi, *wilo;
    cudaGetSymbolAddress(&cahi, g_CAhi);
    cudaGetSymbolAddress(&calo, g_CAlo);
    cudaGetSymbolAddress(&wghi, g_Wghi);
    cudaGetSymbolAddress(&wglo, g_Wglo);
    cudaGetSymbolAddress(&wihi, g_Wihi);
    cudaGetSymbolAddress(&wilo, g_Wilo);

    cudaFuncSetAttribute(gemm_mma<false>, cudaFuncAttributeMaxDynamicSharedMemorySize, SMEM_TOTAL);
    cudaFuncSetAttribute(gemm_mma<true>,  cudaFuncAttributeMaxDynamicSharedMemorySize, SMEM_TOTAL);

    convertA<<<(Bb * 512) / 256, 256>>>((const float4*)input, (const float4*)state,
                                        (float4*)concat);
    convertW<<<(HH * KG / 4) / 256, 256>>>((const float4*)gate_w,
                                           (__nv_bfloat16*)wghi, (__nv_bfloat16*)wglo,
                                           HH * KG / 4);
    convertW<<<(HH * INN / 4) / 256, 256>>>((const float4*)w_i,
                                            (__nv_bfloat16*)wihi, (__nv_bfloat16*)wilo,
                                            HH * INN / 4);

    dim3 grid(HH / BN, Bb / BM);  // (16, 64)
    gemm_mma<false><<<grid, NTH, SMEM_TOTAL>>>(
        (const __nv_bfloat16*)cahi, (const __nv_bfloat16*)calo,
        (const __nv_bfloat16*)wihi, (const __nv_bfloat16*)wilo, INN,
        nullptr, nullptr, nullptr, values, nullptr, nullptr, nullptr);

    gemm_mma<true><<<grid, NTH, SMEM_TOTAL>>>(
        (const __nv_bfloat16*)cahi, (const __nv_bfloat16*)calo,
        (const __nv_bfloat16*)wghi, (const __nv_bfloat16*)wglo, KG,
        state, gate_b, values, pre_gate, gate, pre_h, new_h);
}

// round 4
// speedup vs baseline: 3.3496x; 1.0253x over previous
#include <cuda_runtime.h>
#include <cuda_bf16.h>
#include <cstdint>

#define DI __device__ __forceinline__

namespace {
constexpr int Bb = 8192, INN = 2048, HH = 2048, KG = 4096;
constexpr int BM = 128, BN = 128, BK = 64;       // bf16 elems per K-chunk
constexpr int NTH = 256;                          // 8 warps: 2 (M) x 4 (N)
constexpr int STG_BYTES = 64 * 1024;              // Ah/Al/Wh/Wl 16KB each
constexpr int OFF_AL = 16384, OFF_WH = 32768, OFF_WL = 49152;
constexpr int NSTAGE = 3;
constexpr int SMEM_TOTAL = NSTAGE * STG_BYTES;    // 192KB
}

// bf16 hi/lo scratch
__device__ __align__(1024) __nv_bfloat16 g_CAhi[(size_t)Bb * KG];
__device__ __align__(1024) __nv_bfloat16 g_CAlo[(size_t)Bb * KG];
__device__ __align__(1024) __nv_bfloat16 g_Wghi[(size_t)HH * KG];
__device__ __align__(1024) __nv_bfloat16 g_Wglo[(size_t)HH * KG];
__device__ __align__(1024) __nv_bfloat16 g_Wihi[(size_t)HH * INN];
__device__ __align__(1024) __nv_bfloat16 g_Wilo[(size_t)HH * INN];

// ---------------- PTX helpers ----------------
DI uint32_t smem_u32(const void* p) {
    uint32_t a;
    asm("{ .reg .u64 t; cvta.to.shared.u64 t, %1; cvt.u32.u64 %0, t; }" : "=r"(a) : "l"(p));
    return a;
}
DI void cp16(uint32_t s, const void* g) {
    asm volatile("cp.async.cg.shared.global [%0], [%1], 16;" :: "r"(s), "l"(g) : "memory");
}
DI void cp_commit() { asm volatile("cp.async.commit_group;" ::: "memory"); }
template <int N>
DI void cp_wait() { asm volatile("cp.async.wait_group %0;" :: "n"(N) : "memory"); }

DI void ldsm_x4(uint32_t* r, uint32_t addr) {
    asm volatile("ldmatrix.sync.aligned.m8n8.x4.shared.b16 {%0,%1,%2,%3}, [%4];"
                 : "=r"(r[0]), "=r"(r[1]), "=r"(r[2]), "=r"(r[3]) : "r"(addr));
}
DI void mma_bf16(float* d, const uint32_t* a, const uint32_t* b) {
    asm volatile(
        "mma.sync.aligned.m16n8k16.row.col.f32.bf16.bf16.f32 "
        "{%0,%1,%2,%3}, {%4,%5,%6,%7}, {%8,%9}, {%0,%1,%2,%3};"
        : "+f"(d[0]), "+f"(d[1]), "+f"(d[2]), "+f"(d[3])
        : "r"(a[0]), "r"(a[1]), "r"(a[2]), "r"(a[3]), "r"(b[0]), "r"(b[1]));
}

// swizzled byte offset for (row, 16B-chunk c16) in a 128B-row tile
DI uint32_t swz(int row, int c16) {
    return (uint32_t)(row * 128 + ((c16 ^ (row & 7)) << 4));
}

// ---------------- conversion kernels ----------------
DI void hilo4(float4 v, __nv_bfloat162* h, __nv_bfloat162* l) {
    __nv_bfloat162 h0 = __floats2bfloat162_rn(v.x, v.y);
    __nv_bfloat162 h1 = __floats2bfloat162_rn(v.z, v.w);
    float r0 = v.x - __low2float(h0), r1 = v.y - __high2float(h0);
    float r2 = v.z - __low2float(h1), r3 = v.w - __high2float(h1);
    h[0] = h0; h[1] = h1;
    l[0] = __floats2bfloat162_rn(r0, r1);
    l[1] = __floats2bfloat162_rn(r2, r3);
}

__global__ __launch_bounds__(256) void convertA(
    const float4* __restrict__ in4, const float4* __restrict__ st4,
    float4* __restrict__ concat4)
{
    int idx = blockIdx.x * blockDim.x + threadIdx.x;  // Bb*512
    int row = idx >> 9, c4 = idx & 511;

    float4 vi = in4[(size_t)row * 512 + c4];
    concat4[(size_t)row * 1024 + c4] = vi;
    size_t off = (size_t)row * KG + (size_t)c4 * 4;
    hilo4(vi, (__nv_bfloat162*)(g_CAhi + off), (__nv_bfloat162*)(g_CAlo + off));

    float4 vs = st4[(size_t)row * 512 + c4];
    concat4[(size_t)row * 1024 + 512 + c4] = vs;
    off += INN;
    hilo4(vs, (__nv_bfloat162*)(g_CAhi + off), (__nv_bfloat162*)(g_CAlo + off));
}

__global__ __launch_bounds__(256) void convertW(
    const float4* __restrict__ src, __nv_bfloat16* __restrict__ hi,
    __nv_bfloat16* __restrict__ lo, int n4)
{
    int idx = blockIdx.x * blockDim.x + threadIdx.x;
    if (idx >= n4) return;
    float4 v = src[idx];
    size_t off = (size_t)idx * 4;
    hilo4(v, (__nv_bfloat162*)(hi + off), (__nv_bfloat162*)(lo + off));
}

// ---------------- GEMM via mma.sync ----------------
DI void load_stage(uint32_t st,
                   const __nv_bfloat16* __restrict__ Ahi, const __nv_bfloat16* __restrict__ Alo,
                   const __nv_bfloat16* __restrict__ Whi, const __nv_bfloat16* __restrict__ Wlo,
                   int lda, int ldw, int bm, int bn, int kc, int t)
{
    const int r0 = t >> 2, cc = t & 3;
    #pragma unroll
    for (int j = 0; j < 2; j++) {
        const int r = r0 + 64 * j;
        const char* pAh = (const char*)(Ahi + (size_t)(bm + r) * lda + kc);
        const char* pAl = (const char*)(Alo + (size_t)(bm + r) * lda + kc);
        const char* pWh = (const char*)(Whi + (size_t)(bn + r) * ldw + kc);
        const char* pWl = (const char*)(Wlo + (size_t)(bn + r) * ldw + kc);
        #pragma unroll
        for (int i = 0; i < 2; i++) {
            const int c16 = cc + 4 * i;
            const uint32_t so = swz(r, c16);
            cp16(st + so,          pAh + c16 * 16);
            cp16(st + OFF_AL + so, pAl + c16 * 16);
            cp16(st + OFF_WH + so, pWh + c16 * 16);
            cp16(st + OFF_WL + so, pWl + c16 * 16);
        }
    }
}

template <bool GATE>
__global__ __launch_bounds__(NTH, 1)
void gemm_mma(const __nv_bfloat16* __restrict__ Ahi, const __nv_bfloat16* __restrict__ Alo,
              const __nv_bfloat16* __restrict__ Whi, const __nv_bfloat16* __restrict__ Wlo,
              int kdim,
              const float* __restrict__ state, const float* __restrict__ bias,
              const float* __restrict__ values_in,
              float* __restrict__ out0,
              float* __restrict__ gate_o, float* __restrict__ pre_h_o,
              float* __restrict__ new_h_o)
{
    extern __shared__ char smem[];
    const uint32_t sb = smem_u32(smem);
    const int t = threadIdx.x, wid = t >> 5, lane = t & 31;
    const int warp_m = wid >> 2, warp_n = wid & 3;      // 2 x 4
    const int bm = blockIdx.y * BM, bn = blockIdx.x * BN;

    float acc[4][4][4] = {};   // [mtile][ntile][frag]

    const int nch = kdim / BK;

    // prologue: stages 0 and 1
    load_stage(sb, Ahi, Alo, Whi, Wlo, KG, kdim, bm, bn, 0, t);
    cp_commit();
    load_stage(sb + STG_BYTES, Ahi, Alo, Whi, Wlo, KG, kdim, bm, bn, BK, t);
    cp_commit();

    // ldmatrix lane addressing
    const int a_row = warp_m * 64 + (lane & 15);        // + mt*16
    const int a_chi = lane >> 4;                        // c16 += 2s
    const int lm = lane >> 3;
    const int b_row = warp_n * 32 + (lane & 7) + ((lm >> 1) << 3);  // + np*16
    const int b_chi = lm & 1;

    int s_cur = 0, s_nxt = 2;   // stage index of k, and of k+2
    for (int k = 0; k < nch; k++) {
        if (k + 1 < nch) cp_wait<1>(); else cp_wait<0>();
        __syncthreads();

        // issue loads for chunk k+2 into stage s_nxt (safe: that buffer was
        // last read in iter k-1, and all warps passed the barrier above)
        if (k + 2 < nch) {
            load_stage(sb + s_nxt * STG_BYTES, Ahi, Alo, Whi, Wlo,
                       KG, kdim, bm, bn, (k + 2) * BK, t);
            cp_commit();
        }

        const uint32_t st = sb + s_cur * STG_BYTES;
        #pragma unroll
        for (int s = 0; s < 4; s++) {
            uint32_t ah[4][4], al[4][4];
            #pragma unroll
            for (int mt = 0; mt < 4; mt++) {
                const uint32_t off = swz(a_row + mt * 16, 2 * s + a_chi);
                ldsm_x4(ah[mt], st + off);
                ldsm_x4(al[mt], st + OFF_AL + off);
            }
            uint32_t bh[2][4], bl[2][4];
            #pragma unroll
            for (int np = 0; np < 2; np++) {
                const uint32_t off = swz(b_row + np * 16, 2 * s + b_chi);
                ldsm_x4(bh[np], st + OFF_WH + off);
                ldsm_x4(bl[np], st + OFF_WL + off);
            }
            // term-major: 16 independent MMAs between reuses of any acc
            #pragma unroll
            for (int mt = 0; mt < 4; mt++)
                #pragma unroll
                for (int nt = 0; nt < 4; nt++)
                    mma_bf16(acc[mt][nt], ah[mt], bh[nt >> 1] + (nt & 1) * 2);
            #pragma unroll
            for (int mt = 0; mt < 4; mt++)
                #pragma unroll
                for (int nt = 0; nt < 4; nt++)
                    mma_bf16(acc[mt][nt], ah[mt], bl[nt >> 1] + (nt & 1) * 2);
            #pragma unroll
            for (int mt = 0; mt < 4; mt++)
                #pragma unroll
                for (int nt = 0; nt < 4; nt++)
                    mma_bf16(acc[mt][nt], al[mt], bh[nt >> 1] + (nt & 1) * 2);
        }

        s_cur = (s_cur == NSTAGE - 1) ? 0 : s_cur + 1;
        s_nxt = (s_nxt == NSTAGE - 1) ? 0 : s_nxt + 1;
    }

    // epilogue
    const int er = bm + warp_m * 64 + (lane >> 2);
    const int ec = bn + warp_n * 32 + (lane & 3) * 2;

    #pragma unroll
    for (int mt = 0; mt < 4; mt++) {
        #pragma unroll
        for (int half = 0; half < 2; half++) {
            const size_t row = (size_t)(er + mt * 16 + half * 8) * HH;
            #pragma unroll
            for (int nt = 0; nt < 4; nt++) {
                const int n = ec + nt * 8;
                const float* a2 = &acc[mt][nt][half * 2];
                if (!GATE) {
                    float2 v = { tanhf(a2[0]), tanhf(a2[1]) };
                    *(float2*)(&out0[row + n]) = v;
                } else {
                    float2 bi = *(const float2*)(&bias[n]);
                    float2 sv = *(const float2*)(&state[row + n]);
                    float2 vv = *(const float2*)(&values_in[row + n]);
                    float2 pg = { a2[0] + bi.x, a2[1] + bi.y };
                    float2 g  = { fminf(fmaxf(pg.x, 0.f), 1.f), fminf(fmaxf(pg.y, 0.f), 1.f) };
                    float2 ph = { sv.x * (1.f - g.x) + vv.x * g.x,
                                  sv.y * (1.f - g.y) + vv.y * g.y };
                    float2 nh = { fmaxf(ph.x, 0.f), fmaxf(ph.y, 0.f) };
                    *(float2*)(&out0[row + n])    = pg;
                    *(float2*)(&gate_o[row + n])  = g;
                    *(float2*)(&pre_h_o[row + n]) = ph;
                    *(float2*)(&new_h_o[row + n]) = nh;
                }
            }
        }
    }
}

// ---------------- launch ----------------
extern "C" void kernel_launch(void* const* d_in, const int* in_sizes, int n_in,
                              void* d_out, int out_size) {
    const float* input  = (const float*)d_in[0];
    const float* state  = (const float*)d_in[1];
    const float* gate_w = (const float*)d_in[2];
    const float* gate_b = (const float*)d_in[3];
    const float* w_i    = (const float*)d_in[4];

    float* out = (float*)d_out;
    float* new_h    = out;
    float* concat   = new_h + (size_t)Bb * HH;
    float* pre_gate = concat + (size_t)Bb * KG;
    float* gate     = pre_gate + (size_t)Bb * HH;
    float* values   = gate + (size_t)Bb * HH;
    float* pre_h    = values + (size_t)Bb * HH;

    void *cahi, *calo, *wghi, *wglo, *wihi, *wilo;
    cudaGetSymbolAddress(&cahi, g_CAhi);
    cudaGetSymbolAddress(&calo, g_CAlo);
    cudaGetSymbolAddress(&wghi, g_Wghi);
    cudaGetSymbolAddress(&wglo, g_Wglo);
    cudaGetSymbolAddress(&wihi, g_Wihi);
    cudaGetSymbolAddress(&wilo, g_Wilo);

    cudaFuncSetAttribute(gemm_mma<false>, cudaFuncAttributeMaxDynamicSharedMemorySize, SMEM_TOTAL);
    cudaFuncSetAttribute(gemm_mma<true>,  cudaFuncAttributeMaxDynamicSharedMemorySize, SMEM_TOTAL);

    convertA<<<(Bb * 512) / 256, 256>>>((const float4*)input, (const float4*)state,
                                        (float4*)concat);
    convertW<<<(HH * KG / 4) / 256, 256>>>((const float4*)gate_w,
                                           (__nv_bfloat16*)wghi, (__nv_bfloat16*)wglo,
                                           HH * KG / 4);
    convertW<<<(HH * INN / 4) / 256, 256>>>((const float4*)w_i,
                                            (__nv_bfloat16*)wihi, (__nv_bfloat16*)wilo,
                                            HH * INN / 4);

    dim3 grid(HH / BN, Bb / BM);  // (16, 64)
    gemm_mma<false><<<grid, NTH, SMEM_TOTAL>>>(
        (const __nv_bfloat16*)cahi, (const __nv_bfloat16*)calo,
        (const __nv_bfloat16*)wihi, (const __nv_bfloat16*)wilo, INN,
        nullptr, nullptr, nullptr, values, nullptr, nullptr, nullptr);

    gemm_mma<true><<<grid, NTH, SMEM_TOTAL>>>(
        (const __nv_bfloat16*)cahi, (const __nv_bfloat16*)calo,
        (const __nv_bfloat16*)wghi, (const __nv_bfloat16*)wglo, KG,
        state, gate_b, values, pre_gate, gate, pre_h, new_h);
}